// round 15
// baseline (speedup 1.0000x reference)
#include <cuda_runtime.h>
#include <cuda_fp16.h>
#include <math.h>
#include <stdint.h>

#define Bn 8
#define Hn 96
#define Wn 96
#define Dn 256
#define NPIX (Bn*Hn*Wn)          // 73728
#define NCH 96

typedef unsigned long long u64;

// ---------------- scratch (device globals) ------------------------------------
__device__ __half g_xin[NPIX*Dn];
__device__ __half g_gate[NPIX*Dn];
__device__ __half g_u[NPIX*Dn];
__device__ __half g_y[NPIX*Dn];
__device__ __half g_a16[NPIX*Dn];
// per-chunk per-half local finals: [o][{lf_a,lf_b,P_a,P_b}][b][chunk][c]
__device__ float  g_fin[2][4][Bn][NCH][Dn];
__device__ float  g_carry[2][2][Bn][NCH][Dn];            // chunk-level carry-ins
__device__ float  g_gf[2][2][Bn][12][Dn];                // group finals
__device__ __half g_wiT[512*256];                        // w_in^T [n][k] fp16
__device__ __half g_woT[256*256];                        // w_out^T [n][k] fp16

__device__ __forceinline__ float sigmoidf_(float v){
    return __fdividef(1.f, 1.f + __expf(-v));
}

__device__ __forceinline__ uint32_t smem_u32(const void* p){
    uint32_t a;
    asm("{ .reg .u64 t; cvta.to.shared.u64 t, %1; cvt.u32.u64 %0, t; }" : "=r"(a) : "l"(p));
    return a;
}
__device__ __forceinline__ void cp16(uint32_t sdst, const void* gsrc){
    asm volatile("cp.async.cg.shared.global [%0], [%1], 16;" :: "r"(sdst), "l"(gsrc));
}
__device__ __forceinline__ void ldsm4(uint32_t* r, uint32_t a){
    asm volatile("ldmatrix.sync.aligned.m8n8.x4.shared.b16 {%0,%1,%2,%3}, [%4];"
        : "=r"(r[0]),"=r"(r[1]),"=r"(r[2]),"=r"(r[3]) : "r"(a));
}
__device__ __forceinline__ void mma16816h(float* d, const uint32_t* a, const uint32_t* b){
    asm volatile("mma.sync.aligned.m16n8k16.row.col.f32.f16.f16.f32 "
        "{%0,%1,%2,%3}, {%4,%5,%6,%7}, {%8,%9}, {%0,%1,%2,%3};"
        : "+f"(d[0]), "+f"(d[1]), "+f"(d[2]), "+f"(d[3])
        : "r"(a[0]), "r"(a[1]), "r"(a[2]), "r"(a[3]), "r"(b[0]), "r"(b[1]));
}

// =============== scanB1 body: chunk-level carry scans from half finals =========
__device__ __forceinline__ void scanB1_body(const float* a_logit, int b, int o, int g, int tid)
{
    int c = tid * 2;
    float2 al = *(const float2*)(a_logit + c);
    float ax = fminf(fmaxf(sigmoidf_(al.x), 1e-4f), 1.f - 1e-4f);
    float ay = fminf(fmaxf(sigmoidf_(al.y), 1e-4f), 1.f - 1e-4f);
    float a48x = (float)exp(48.0 * log((double)ax));
    float a48y = (float)exp(48.0 * log((double)ay));
    float a96x = a48x*a48x, a96y = a48y*a48y;

    float2 lf[8], Pv[8];
    #pragma unroll
    for (int i = 0; i < 8; i++) {
        int ch = g*8 + i;
        float2 lfa = *(const float2*)&g_fin[o][0][b][ch][c];
        float2 lfb = *(const float2*)&g_fin[o][1][b][ch][c];
        float2 Pa  = *(const float2*)&g_fin[o][2][b][ch][c];
        float2 Pb  = *(const float2*)&g_fin[o][3][b][ch][c];
        lf[i] = make_float2(a48x*lfa.x + lfb.x, a48y*lfa.y + lfb.y);
        Pv[i] = make_float2(Pa.x + a48x*Pb.x, Pa.y + a48y*Pb.y);
    }
    float cx = 0.f, cy = 0.f;
    #pragma unroll
    for (int i = 0; i < 8; i++) {
        *(float2*)&g_carry[o][0][b][g*8 + i][c] = make_float2(cx, cy);
        cx = a96x*cx + lf[i].x;  cy = a96y*cy + lf[i].y;
    }
    *(float2*)&g_gf[o][0][b][g][c] = make_float2(cx, cy);

    cx = 0.f; cy = 0.f;
    #pragma unroll
    for (int i = 7; i >= 0; i--) {
        *(float2*)&g_carry[o][1][b][g*8 + i][c] = make_float2(cx, cy);
        cx = a96x*cx + Pv[i].x;  cy = a96y*cy + Pv[i].y;
    }
    *(float2*)&g_gf[o][1][b][g][c] = make_float2(cx, cy);
}

// =============== prep: LN -> fp16 A; plus fused weight transpose ===============
__global__ __launch_bounds__(256) void k_ln_split(
    const float* __restrict__ x, const float* __restrict__ ln_g,
    const float* __restrict__ ln_b, const float* __restrict__ w_in,
    const float* __restrict__ w_out)
{
    if (blockIdx.x >= NPIX/32) {
        int n = blockIdx.x - NPIX/32;
        int k = threadIdx.x;
        if (n < 512) {
            g_wiT[(size_t)n*256 + k] = __float2half_rn(w_in[(size_t)k * 512 + n]);
        } else {
            int nn = n - 512;
            g_woT[(size_t)nn*256 + k] = __float2half_rn(w_out[(size_t)k * 256 + nn]);
        }
        return;
    }
    int tid = threadIdx.x, lane = tid & 31, warp = tid >> 5;
    #pragma unroll
    for (int rr = 0; rr < 4; rr++) {
        int row = blockIdx.x * 32 + warp * 4 + rr;
        const float* xr = x + (size_t)row * Dn;
        float4 v0 = *(const float4*)(xr + lane*4);
        float4 v1 = *(const float4*)(xr + 128 + lane*4);
        float s  = v0.x+v0.y+v0.z+v0.w + v1.x+v1.y+v1.z+v1.w;
        float s2 = v0.x*v0.x+v0.y*v0.y+v0.z*v0.z+v0.w*v0.w
                 + v1.x*v1.x+v1.y*v1.y+v1.z*v1.z+v1.w*v1.w;
        #pragma unroll
        for (int off = 16; off; off >>= 1) {
            s  += __shfl_xor_sync(0xffffffffu, s,  off);
            s2 += __shfl_xor_sync(0xffffffffu, s2, off);
        }
        float mu = s * (1.f/256.f);
        float rstd = rsqrtf(s2 * (1.f/256.f) - mu*mu + 1e-5f);
        #pragma unroll
        for (int half = 0; half < 2; half++) {
            int col = half*128 + lane*4;
            float4 v = half ? v1 : v0;
            float4 gg = *(const float4*)(ln_g + col);
            float4 bb = *(const float4*)(ln_b + col);
            __half2 p0 = __floats2half2_rn((v.x - mu)*rstd*gg.x + bb.x,
                                           (v.y - mu)*rstd*gg.y + bb.y);
            __half2 p1 = __floats2half2_rn((v.z - mu)*rstd*gg.z + bb.z,
                                           (v.w - mu)*rstd*gg.w + bb.w);
            __half2* dst = (__half2*)(g_a16 + (size_t)row*Dn + col);
            dst[0] = p0; dst[1] = p1;
        }
    }
}

// =============== HMMA fp16 single-term GEMM (2 CTAs/SM) ========================
#define TILE_B 16384
#define BUF_B  (2*TILE_B)
#define SMEM_GEMM (2*BUF_B)

__device__ __forceinline__ void load_chunk(
    uint32_t sbuf, const __half* __restrict__ A, const __half* __restrict__ B,
    int m0, int n0, int kc, int tid)
{
    #pragma unroll
    for (int t = 0; t < 2; t++) {
        const __half* src = t ? B : A;
        int r0 = t ? n0 : m0;
        #pragma unroll
        for (int q = 0; q < 4; q++) {
            int u = q*256 + tid;
            int r = u >> 3, g = u & 7;
            uint32_t boff = r*128 + g*16;
            uint32_t swo = boff ^ ((boff>>3)&0x70);
            cp16(sbuf + t*TILE_B + swo, src + (size_t)(r0 + r)*Dn + kc + g*8);
        }
    }
}

__device__ __forceinline__ void compute_chunk(
    uint32_t sbuf, float acc[4][4][4], int wm, int wn, int lane)
{
    uint32_t aA = sbuf, aB = sbuf + TILE_B;
    int arow = wm + (lane&7) + 8*((lane>>3)&1);
    int akb0 = 16*(lane>>4);
    int brow = wn + 8*(lane>>4) + (lane&7);
    int bkb0 = 16*((lane>>3)&1);
    #pragma unroll
    for (int ks = 0; ks < 4; ks++) {
        int kb = ks*32;
        uint32_t ah[4][4], bh[4][2];
        #pragma unroll
        for (int mt = 0; mt < 4; mt++) {
            uint32_t boff = (uint32_t)(arow + mt*16)*128 + kb + akb0;
            uint32_t swo = boff ^ ((boff>>3)&0x70);
            ldsm4(ah[mt], aA + swo);
        }
        #pragma unroll
        for (int p = 0; p < 2; p++) {
            uint32_t boff = (uint32_t)(brow + p*16)*128 + kb + bkb0;
            uint32_t swo = boff ^ ((boff>>3)&0x70);
            uint32_t t[4];
            ldsm4(t, aB + swo);
            bh[p*2][0]=t[0]; bh[p*2][1]=t[1]; bh[p*2+1][0]=t[2]; bh[p*2+1][1]=t[3];
        }
        #pragma unroll
        for (int mt = 0; mt < 4; mt++)
            #pragma unroll
            for (int nt = 0; nt < 4; nt++)
                mma16816h(acc[mt][nt], ah[mt], bh[nt]);
    }
}

__global__ __launch_bounds__(256, 2) void k_gemm(
    int mode, const float* __restrict__ bias,
    const float* __restrict__ xres, float* __restrict__ outp)
{
    extern __shared__ char smem[];
    uint32_t sb = smem_u32(smem);
    int tid = threadIdx.x, lane = tid & 31, wid = tid >> 5;
    int n0 = blockIdx.x * 128, m0 = blockIdx.y * 128;
    int wm = (wid & 1) * 64, wn = (wid >> 1) * 32;
    const __half* B = mode ? g_woT : g_wiT;
    uint32_t buf0 = sb, buf1 = sb + BUF_B;
    float acc[4][4][4] = {};

    load_chunk(buf0, g_a16, B, m0, n0, 0, tid);
    asm volatile("cp.async.commit_group;" ::: "memory");
    load_chunk(buf1, g_a16, B, m0, n0, 64, tid);
    asm volatile("cp.async.commit_group;" ::: "memory");

    asm volatile("cp.async.wait_group 1;" ::: "memory");
    __syncthreads();
    compute_chunk(buf0, acc, wm, wn, lane);
    __syncthreads();
    load_chunk(buf0, g_a16, B, m0, n0, 128, tid);
    asm volatile("cp.async.commit_group;" ::: "memory");

    asm volatile("cp.async.wait_group 1;" ::: "memory");
    __syncthreads();
    compute_chunk(buf1, acc, wm, wn, lane);
    __syncthreads();
    load_chunk(buf1, g_a16, B, m0, n0, 192, tid);
    asm volatile("cp.async.commit_group;" ::: "memory");

    asm volatile("cp.async.wait_group 1;" ::: "memory");
    __syncthreads();
    compute_chunk(buf0, acc, wm, wn, lane);

    asm volatile("cp.async.wait_group 0;" ::: "memory");
    __syncthreads();
    compute_chunk(buf1, acc, wm, wn, lane);

    #pragma unroll
    for (int mt = 0; mt < 4; mt++) {
        int r0 = m0 + wm + mt*16 + (lane >> 2);
        #pragma unroll
        for (int nt = 0; nt < 4; nt++) {
            int col = n0 + wn + nt*8 + (lane & 3)*2;
            float2 bv = *(const float2*)(bias + col);
            float v0 = acc[mt][nt][0] + bv.x, v1 = acc[mt][nt][1] + bv.y;
            float v2 = acc[mt][nt][2] + bv.x, v3 = acc[mt][nt][3] + bv.y;
            if (mode == 0) {
                if (col >= 256) {
                    *(__half2*)(g_gate + (size_t)r0*Dn + col - 256) =
                        __floats2half2_rn(sigmoidf_(v0), sigmoidf_(v1));
                    *(__half2*)(g_gate + (size_t)(r0+8)*Dn + col - 256) =
                        __floats2half2_rn(sigmoidf_(v2), sigmoidf_(v3));
                } else {
                    *(__half2*)(g_xin + (size_t)r0*Dn + col) = __floats2half2_rn(v0, v1);
                    *(__half2*)(g_xin + (size_t)(r0+8)*Dn + col) = __floats2half2_rn(v2, v3);
                }
            } else {
                float2 x0 = *(const float2*)(xres + (size_t)r0*Dn + col);
                float2 x1 = *(const float2*)(xres + (size_t)(r0+8)*Dn + col);
                float2 o0 = {v0 + x0.x, v1 + x0.y};
                float2 o1 = {v2 + x1.x, v3 + x1.y};
                *(float2*)(outp + (size_t)r0*Dn + col) = o0;
                *(float2*)(outp + (size_t)(r0+8)*Dn + col) = o1;
            }
        }
    }
}

// =============== conv3x3+SiLU + ROW half-chunk scan (half-row per block) =======
// grid (Hn*2, Bn), 256 thr. Each block does 48 output cols + half-scan.
__global__ __launch_bounds__(256) void k_conv_rowscan(
    const float* __restrict__ conv_w, const float* __restrict__ conv_b,
    const float* __restrict__ a_logit, const float* __restrict__ ssm_b)
{
    int c = threadIdx.x;
    int h = blockIdx.x >> 1, hf = blockIdx.x & 1;
    int b = blockIdx.y;
    int c0 = hf * 48;                       // first output col of this half

    float kw[3][3];
    const __half* rp[3];
    #pragma unroll
    for (int dh = 0; dh < 3; dh++) {
        int hh = h + dh - 1;
        bool v = (hh >= 0 && hh < Hn);
        float m = v ? 1.f : 0.f;
        #pragma unroll
        for (int dw = 0; dw < 3; dw++)
            kw[dh][dw] = m * conv_w[(dh*3 + dw) * Dn + c];
        rp[dh] = g_xin + ((size_t)(b*Hn + (v ? hh : 0)) * Wn) * Dn + c;
    }
    float bias = conv_b[c];

    float a = fminf(fmaxf(sigmoidf_(a_logit[c]), 1e-4f), 1.f - 1e-4f);
    float bb = ssm_b[c];
    float lf = 0.f, P = 0.f, ap = 1.f;

    float cA[3], cB[3];
    #pragma unroll
    for (int dh = 0; dh < 3; dh++) {
        cA[dh] = hf ? __half2float(rp[dh][(size_t)(c0-1) * Dn]) : 0.f;
        cB[dh] = __half2float(rp[dh][(size_t)c0 * Dn]);
    }

    __half* up = g_u + ((size_t)((b*Hn + h) * Wn) + c0) * Dn + c;

    for (int g = 0; g < 6; g++) {
        float nw[3][8];
        #pragma unroll
        for (int i = 0; i < 8; i++) {
            int col = c0 + g*8 + 1 + i;
            bool ok = (col < Wn);
            int colc = ok ? col : (Wn-1);
            #pragma unroll
            for (int dh = 0; dh < 3; dh++)
                nw[dh][i] = ok ? __half2float(rp[dh][(size_t)colc * Dn]) : 0.f;
        }
        float seq[3][10];
        #pragma unroll
        for (int dh = 0; dh < 3; dh++) {
            seq[dh][0] = cA[dh]; seq[dh][1] = cB[dh];
            #pragma unroll
            for (int i = 0; i < 8; i++) seq[dh][2+i] = nw[dh][i];
        }
        #pragma unroll
        for (int i = 0; i < 8; i++) {
            float s = bias;
            #pragma unroll
            for (int dh = 0; dh < 3; dh++) {
                s += kw[dh][0]*seq[dh][i] + kw[dh][1]*seq[dh][i+1] + kw[dh][2]*seq[dh][i+2];
            }
            float u = s * sigmoidf_(s);
            up[(size_t)(g*8 + i) * Dn] = __float2half_rn(u);
            float bu = bb * u;
            lf = a * lf + bu;
            P  = fmaf(ap, bu, P);
            ap *= a;
        }
        #pragma unroll
        for (int dh = 0; dh < 3; dh++) { cA[dh] = seq[dh][8]; cB[dh] = seq[dh][9]; }
    }
    g_fin[0][0 + hf][b][h][c] = lf;     // lf_a / lf_b
    g_fin[0][2 + hf][b][h][c] = P;      // P_a / P_b
}

// =============== K3a: col half local finals + fused scanB1(o=0) ===============
// grid (192 + 12, Bn), 128 thr (float2).
__global__ __launch_bounds__(128) void k_scanA_col(
    const float* __restrict__ a_logit, const float* __restrict__ ssm_b)
{
    if (blockIdx.x >= 192) {
        scanB1_body(a_logit, blockIdx.y, 0, blockIdx.x - 192, threadIdx.x);
        return;
    }
    int c = threadIdx.x * 2;
    int j = blockIdx.x >> 1, hf = blockIdx.x & 1;
    int b = blockIdx.y;
    float2 al = *(const float2*)(a_logit + c);
    float ax = fminf(fmaxf(sigmoidf_(al.x), 1e-4f), 1.f - 1e-4f);
    float ay = fminf(fmaxf(sigmoidf_(al.y), 1e-4f), 1.f - 1e-4f);
    float2 bb = *(const float2*)(ssm_b + c);

    size_t base = ((size_t)b*Hn*Wn + (size_t)(hf*48)*Wn + j) * Dn + c;
    const size_t stride = (size_t)Wn * Dn;

    float lfx=0.f, lfy=0.f, Px=0.f, Py=0.f, apx=1.f, apy=1.f;
    for (int g = 0; g < 3; g++) {
        __half2 t[16];
        #pragma unroll
        for (int i = 0; i < 16; i++) t[i] = *(const __half2*)(g_u + base + (size_t)(g*16 + i)*stride);
        #pragma unroll
        for (int i = 0; i < 16; i++) {
            float2 f = __half22float2(t[i]);
            float bux = bb.x * f.x, buy = bb.y * f.y;
            lfx = ax*lfx + bux;  lfy = ay*lfy + buy;
            Px = fmaf(apx, bux, Px); Py = fmaf(apy, buy, Py);
            apx *= ax; apy *= ay;
        }
    }
    *(float2*)&g_fin[1][0 + hf][b][j][c] = make_float2(lfx, lfy);
    *(float2*)&g_fin[1][2 + hf][b][j][c] = make_float2(Px, Py);
}

// =============== K3c: half-chunk apply pass; o==0 grid fuses scanB1(o=1) ======
__global__ __launch_bounds__(128) void k_scanC(
    const float* __restrict__ a_logit, const float* __restrict__ ssm_b,
    const float* __restrict__ ssm_c,  const float* __restrict__ ssm_d, int o)
{
    if (blockIdx.x >= 192) {
        scanB1_body(a_logit, blockIdx.y, 1, blockIdx.x - 192, threadIdx.x);
        return;
    }
    int c = threadIdx.x * 2;
    int j = blockIdx.x >> 1, hf = blockIdx.x & 1;
    int b = blockIdx.y;
    int gq = j >> 3, iq = j & 7;
    float2 al = *(const float2*)(a_logit + c);
    float ax = fminf(fmaxf(sigmoidf_(al.x), 1e-4f), 1.f - 1e-4f);
    float ay = fminf(fmaxf(sigmoidf_(al.y), 1e-4f), 1.f - 1e-4f);
    float invax = 1.f/ax, invay = 1.f/ay;
    float a48x = (float)exp(48.0 * log((double)ax));
    float a48y = (float)exp(48.0 * log((double)ay));
    float a96x = a48x*a48x, a96y = a48y*a48y;
    float a2x = a96x*a96x, a2y = a96y*a96y;
    float a4x = a2x*a2x,  a4y = a2y*a2y;
    float a768x = a4x*a4x, a768y = a4y*a4y;
    float pFx = 1.f, pFy = 1.f, pBx = 1.f, pBy = 1.f;
    for (int k = 0; k < iq; k++)     { pFx *= a96x; pFy *= a96y; }
    for (int k = 0; k < 7 - iq; k++) { pBx *= a96x; pBy *= a96y; }
    float2 bb = *(const float2*)(ssm_b + c);
    float2 cc = *(const float2*)(ssm_c + c);
    float2 dd = *(const float2*)(ssm_d + c);

    // chunk-level carries (group chains from group finals)
    float2 gfv[12], gbv[12];
    #pragma unroll
    for (int g = 0; g < 12; g++) {
        gfv[g] = *(const float2*)&g_gf[o][0][b][g][c];
        gbv[g] = *(const float2*)&g_gf[o][1][b][g][c];
    }
    float gc0x = 0.f, gc0y = 0.f;
    for (int g = 0; g < gq; g++) { gc0x = a768x*gc0x + gfv[g].x; gc0y = a768y*gc0y + gfv[g].y; }
    float gc1x = 0.f, gc1y = 0.f;
    for (int g = 11; g > gq; g--) { gc1x = a768x*gc1x + gbv[g].x; gc1y = a768y*gc1y + gbv[g].y; }

    float2 lc0 = *(const float2*)&g_carry[o][0][b][j][c];
    float2 lc1 = *(const float2*)&g_carry[o][1][b][j][c];
    float Sx = lc0.x + pFx*gc0x, Sy = lc0.y + pFy*gc0y;      // fwd carry into chunk
    float Cx = lc1.x + pBx*gc1x, Cy = lc1.y + pBy*gc1y;      // bwd carry into chunk

    // per-half adjustments
    float2 lfa = *(const float2*)&g_fin[o][0][b][j][c];
    float2 Pa  = *(const float2*)&g_fin[o][2][b][j][c];
    float2 Pb  = *(const float2*)&g_fin[o][3][b][j][c];
    float sfx, sfy, cbNx, cbNy, Ttx, Tty;
    if (hf == 0) {
        sfx = Sx; sfy = Sy;
        cbNx = Pb.x + a48x*Cx;  cbNy = Pb.y + a48y*Cy;
        Ttx = Pa.x; Tty = Pa.y;
    } else {
        sfx = a48x*Sx + lfa.x;  sfy = a48y*Sy + lfa.y;
        cbNx = Cx;              cbNy = Cy;
        Ttx = Pb.x;             Tty = Pb.y;
    }
    float cb48x = a48x * cbNx, cb48y = a48y * cbNy;

    size_t base, stride;
    if (o == 0) { base = ((size_t)((b*Hn + j) * Wn) + hf*48) * Dn + c;             stride = Dn; }
    else        { base = ((size_t)b*Hn*Wn + (size_t)(hf*48)*Wn + j) * Dn + c;      stride = (size_t)Wn * Dn; }

    float Px=0.f, Py=0.f, apx=1.f, apy=1.f, rapx=1.f, rapy=1.f;
    if (o == 0) {
        for (int g = 0; g < 3; g++) {
            __half2 t[16];
            #pragma unroll
            for (int i = 0; i < 16; i++) t[i] = *(const __half2*)(g_u + base + (size_t)(g*16 + i)*stride);
            #pragma unroll
            for (int i = 0; i < 16; i++) {
                size_t addr = base + (size_t)(g*16 + i) * stride;
                float2 uf = __half22float2(t[i]);
                sfx = ax*sfx + bb.x*uf.x;
                sfy = ay*sfy + bb.y*uf.y;
                float sbx = (Ttx - Px + cb48x) * rapx;
                float sby = (Tty - Py + cb48y) * rapy;
                float ctx = 0.25f * cc.x * (sfx + sbx);
                float cty = 0.25f * cc.y * (sfy + sby);
                *(__half2*)(g_y + addr) = __floats2half2_rn(ctx + dd.x*uf.x, cty + dd.y*uf.y);
                Px = fmaf(apx, bb.x*uf.x, Px);
                Py = fmaf(apy, bb.y*uf.y, Py);
                apx *= ax; apy *= ay;
                rapx *= invax; rapy *= invay;
            }
        }
    } else {
        for (int g = 0; g < 6; g++) {
            __half2 t[8], yv[8], gv[8];
            #pragma unroll
            for (int i = 0; i < 8; i++) t[i] = *(const __half2*)(g_u + base + (size_t)(g*8 + i)*stride);
            #pragma unroll
            for (int i = 0; i < 8; i++) yv[i] = *(const __half2*)(g_y + base + (size_t)(g*8 + i)*stride);
            #pragma unroll
            for (int i = 0; i < 8; i++) gv[i] = *(const __half2*)(g_gate + base + (size_t)(g*8 + i)*stride);
            #pragma unroll
            for (int i = 0; i < 8; i++) {
                size_t addr = base + (size_t)(g*8 + i) * stride;
                float2 uf = __half22float2(t[i]);
                sfx = ax*sfx + bb.x*uf.x;
                sfy = ay*sfy + bb.y*uf.y;
                float sbx = (Ttx - Px + cb48x) * rapx;
                float sby = (Tty - Py + cb48y) * rapy;
                float ctx = 0.25f * cc.x * (sfx + sbx);
                float cty = 0.25f * cc.y * (sfy + sby);
                float2 yf = __half22float2(yv[i]);
                float2 gf = __half22float2(gv[i]);
                *(__half2*)(g_a16 + addr) =
                    __floats2half2_rn((yf.x + ctx) * gf.x, (yf.y + cty) * gf.y);
                Px = fmaf(apx, bb.x*uf.x, Px);
                Py = fmaf(apy, bb.y*uf.y, Py);
                apx *= ax; apy *= ay;
                rapx *= invax; rapy *= invay;
            }
        }
    }
}

// ==============================================================================
extern "C" void kernel_launch(void* const* d_in, const int* in_sizes, int n_in,
                              void* d_out, int out_size)
{
    const float* x       = (const float*)d_in[0];
    const float* ln_g    = (const float*)d_in[1];
    const float* ln_b    = (const float*)d_in[2];
    const float* w_in    = (const float*)d_in[3];
    const float* b_in    = (const float*)d_in[4];
    const float* conv_w  = (const float*)d_in[5];
    const float* conv_b  = (const float*)d_in[6];
    const float* a_logit = (const float*)d_in[7];
    const float* ssm_b   = (const float*)d_in[8];
    const float* ssm_c   = (const float*)d_in[9];
    const float* ssm_d   = (const float*)d_in[10];
    const float* w_out   = (const float*)d_in[11];
    const float* b_out   = (const float*)d_in[12];
    float* out = (float*)d_out;

    cudaFuncSetAttribute(k_gemm, cudaFuncAttributeMaxDynamicSharedMemorySize, SMEM_GEMM);

    k_ln_split<<<NPIX/32 + 768, 256>>>(x, ln_g, ln_b, w_in, w_out);
    k_gemm<<<dim3(4, NPIX/128), 256, SMEM_GEMM>>>(0, b_in, nullptr, nullptr);
    k_conv_rowscan<<<dim3(Hn*2, Bn), 256>>>(conv_w, conv_b, a_logit, ssm_b);
    k_scanA_col<<<dim3(192 + 12, Bn), 128>>>(a_logit, ssm_b);
    k_scanC<<<dim3(192 + 12, Bn), 128>>>(a_logit, ssm_b, ssm_c, ssm_d, 0);
    k_scanC<<<dim3(192, Bn), 128>>>(a_logit, ssm_b, ssm_c, ssm_d, 1);
    k_gemm<<<dim3(2, NPIX/128), 256, SMEM_GEMM>>>(1, b_out, x, out);
}

// round 16
// speedup vs baseline: 1.0972x; 1.0972x over previous
#include <cuda_runtime.h>
#include <cuda_fp16.h>
#include <math.h>
#include <stdint.h>

#define Bn 8
#define Hn 96
#define Wn 96
#define Dn 256
#define NPIX (Bn*Hn*Wn)          // 73728
#define NCH 96

typedef unsigned long long u64;

// ---------------- scratch (device globals) ------------------------------------
__device__ __half g_xin[NPIX*Dn];
__device__ __half g_gate[NPIX*Dn];
__device__ __half g_u[NPIX*Dn];
__device__ __half g_y[NPIX*Dn];
__device__ __half g_a16[NPIX*Dn];                        // GEMM A operand (fp16)
__device__ float  g_fin[2][2][Bn][NCH][Dn];
__device__ float  g_carry[2][2][Bn][NCH][Dn];            // in-group local carries
__device__ float  g_gf[2][2][Bn][12][Dn];                // group finals
__device__ __half g_wiT[512*256];                        // w_in^T [n][k] fp16
__device__ __half g_woT[256*256];                        // w_out^T [n][k] fp16

__device__ __forceinline__ float sigmoidf_(float v){
    return __fdividef(1.f, 1.f + __expf(-v));
}

__device__ __forceinline__ uint32_t smem_u32(const void* p){
    uint32_t a;
    asm("{ .reg .u64 t; cvta.to.shared.u64 t, %1; cvt.u32.u64 %0, t; }" : "=r"(a) : "l"(p));
    return a;
}
__device__ __forceinline__ void cp16(uint32_t sdst, const void* gsrc){
    asm volatile("cp.async.cg.shared.global [%0], [%1], 16;" :: "r"(sdst), "l"(gsrc));
}
__device__ __forceinline__ void ldsm4(uint32_t* r, uint32_t a){
    asm volatile("ldmatrix.sync.aligned.m8n8.x4.shared.b16 {%0,%1,%2,%3}, [%4];"
        : "=r"(r[0]),"=r"(r[1]),"=r"(r[2]),"=r"(r[3]) : "r"(a));
}
__device__ __forceinline__ void mma16816h(float* d, const uint32_t* a, const uint32_t* b){
    asm volatile("mma.sync.aligned.m16n8k16.row.col.f32.f16.f16.f32 "
        "{%0,%1,%2,%3}, {%4,%5,%6,%7}, {%8,%9}, {%0,%1,%2,%3};"
        : "+f"(d[0]), "+f"(d[1]), "+f"(d[2]), "+f"(d[3])
        : "r"(a[0]), "r"(a[1]), "r"(a[2]), "r"(a[3]), "r"(b[0]), "r"(b[1]));
}

// =============== scanB1 body (group-local carry scans, float2) =================
__device__ __forceinline__ void scanB1_body(const float* a_logit, int b, int o, int g, int tid)
{
    int c = tid * 2;
    float2 al = *(const float2*)(a_logit + c);
    float ax = fminf(fmaxf(sigmoidf_(al.x), 1e-4f), 1.f - 1e-4f);
    float ay = fminf(fmaxf(sigmoidf_(al.y), 1e-4f), 1.f - 1e-4f);
    float a96x = (float)exp(96.0 * log((double)ax));
    float a96y = (float)exp(96.0 * log((double)ay));

    float2 t[8];
    #pragma unroll
    for (int i = 0; i < 8; i++) t[i] = *(const float2*)&g_fin[o][0][b][g*8 + i][c];
    float cx = 0.f, cy = 0.f;
    #pragma unroll
    for (int i = 0; i < 8; i++) {
        *(float2*)&g_carry[o][0][b][g*8 + i][c] = make_float2(cx, cy);
        cx = a96x*cx + t[i].x;  cy = a96y*cy + t[i].y;
    }
    *(float2*)&g_gf[o][0][b][g][c] = make_float2(cx, cy);

    #pragma unroll
    for (int i = 0; i < 8; i++) t[i] = *(const float2*)&g_fin[o][1][b][g*8 + i][c];
    cx = 0.f; cy = 0.f;
    #pragma unroll
    for (int i = 7; i >= 0; i--) {
        *(float2*)&g_carry[o][1][b][g*8 + i][c] = make_float2(cx, cy);
        cx = a96x*cx + t[i].x;  cy = a96y*cy + t[i].y;
    }
    *(float2*)&g_gf[o][1][b][g][c] = make_float2(cx, cy);
}

// =============== prep: LN -> fp16 A (MLP=8); fused weight transpose ============
__global__ __launch_bounds__(256) void k_ln_split(
    const float* __restrict__ x, const float* __restrict__ ln_g,
    const float* __restrict__ ln_b, const float* __restrict__ w_in,
    const float* __restrict__ w_out)
{
    if (blockIdx.x >= NPIX/32) {
        int n = blockIdx.x - NPIX/32;
        int k = threadIdx.x;
        if (n < 512) {
            g_wiT[(size_t)n*256 + k] = __float2half_rn(w_in[(size_t)k * 512 + n]);
        } else {
            int nn = n - 512;
            g_woT[(size_t)nn*256 + k] = __float2half_rn(w_out[(size_t)k * 256 + nn]);
        }
        return;
    }
    int tid = threadIdx.x, lane = tid & 31, warp = tid >> 5;
    int row0 = blockIdx.x * 32 + warp * 4;

    // batched loads for all 4 rows (8 independent float4 LDGs)
    float4 v[4][2];
    #pragma unroll
    for (int rr = 0; rr < 4; rr++) {
        const float* xr = x + (size_t)(row0 + rr) * Dn;
        v[rr][0] = *(const float4*)(xr + lane*4);
        v[rr][1] = *(const float4*)(xr + 128 + lane*4);
    }

    float4 gg0 = *(const float4*)(ln_g + lane*4);
    float4 gg1 = *(const float4*)(ln_g + 128 + lane*4);
    float4 be0 = *(const float4*)(ln_b + lane*4);
    float4 be1 = *(const float4*)(ln_b + 128 + lane*4);

    #pragma unroll
    for (int rr = 0; rr < 4; rr++) {
        float4 a = v[rr][0], b = v[rr][1];
        float s  = a.x+a.y+a.z+a.w + b.x+b.y+b.z+b.w;
        float s2 = a.x*a.x+a.y*a.y+a.z*a.z+a.w*a.w
                 + b.x*b.x+b.y*b.y+b.z*b.z+b.w*b.w;
        #pragma unroll
        for (int off = 16; off; off >>= 1) {
            s  += __shfl_xor_sync(0xffffffffu, s,  off);
            s2 += __shfl_xor_sync(0xffffffffu, s2, off);
        }
        float mu = s * (1.f/256.f);
        float rstd = rsqrtf(s2 * (1.f/256.f) - mu*mu + 1e-5f);
        __half2 p0 = __floats2half2_rn((a.x - mu)*rstd*gg0.x + be0.x,
                                       (a.y - mu)*rstd*gg0.y + be0.y);
        __half2 p1 = __floats2half2_rn((a.z - mu)*rstd*gg0.z + be0.z,
                                       (a.w - mu)*rstd*gg0.w + be0.w);
        __half2 p2 = __floats2half2_rn((b.x - mu)*rstd*gg1.x + be1.x,
                                       (b.y - mu)*rstd*gg1.y + be1.y);
        __half2 p3 = __floats2half2_rn((b.z - mu)*rstd*gg1.z + be1.z,
                                       (b.w - mu)*rstd*gg1.w + be1.w);
        __half2* d0 = (__half2*)(g_a16 + (size_t)(row0 + rr)*Dn + lane*4);
        __half2* d1 = (__half2*)(g_a16 + (size_t)(row0 + rr)*Dn + 128 + lane*4);
        d0[0] = p0; d0[1] = p1;
        d1[0] = p2; d1[1] = p3;
    }
}

// =============== HMMA fp16 single-term GEMM (2 CTAs/SM) ========================
#define TILE_B 16384
#define BUF_B  (2*TILE_B)
#define SMEM_GEMM (2*BUF_B)

__device__ __forceinline__ void load_chunk(
    uint32_t sbuf, const __half* __restrict__ A, const __half* __restrict__ B,
    int m0, int n0, int kc, int tid)
{
    #pragma unroll
    for (int t = 0; t < 2; t++) {
        const __half* src = t ? B : A;
        int r0 = t ? n0 : m0;
        #pragma unroll
        for (int q = 0; q < 4; q++) {
            int u = q*256 + tid;
            int r = u >> 3, g = u & 7;
            uint32_t boff = r*128 + g*16;
            uint32_t swo = boff ^ ((boff>>3)&0x70);
            cp16(sbuf + t*TILE_B + swo, src + (size_t)(r0 + r)*Dn + kc + g*8);
        }
    }
}

__device__ __forceinline__ void compute_chunk(
    uint32_t sbuf, float acc[4][4][4], int wm, int wn, int lane)
{
    uint32_t aA = sbuf, aB = sbuf + TILE_B;
    int arow = wm + (lane&7) + 8*((lane>>3)&1);
    int akb0 = 16*(lane>>4);
    int brow = wn + 8*(lane>>4) + (lane&7);
    int bkb0 = 16*((lane>>3)&1);
    #pragma unroll
    for (int ks = 0; ks < 4; ks++) {
        int kb = ks*32;
        uint32_t ah[4][4], bh[4][2];
        #pragma unroll
        for (int mt = 0; mt < 4; mt++) {
            uint32_t boff = (uint32_t)(arow + mt*16)*128 + kb + akb0;
            uint32_t swo = boff ^ ((boff>>3)&0x70);
            ldsm4(ah[mt], aA + swo);
        }
        #pragma unroll
        for (int p = 0; p < 2; p++) {
            uint32_t boff = (uint32_t)(brow + p*16)*128 + kb + bkb0;
            uint32_t swo = boff ^ ((boff>>3)&0x70);
            uint32_t t[4];
            ldsm4(t, aB + swo);
            bh[p*2][0]=t[0]; bh[p*2][1]=t[1]; bh[p*2+1][0]=t[2]; bh[p*2+1][1]=t[3];
        }
        #pragma unroll
        for (int mt = 0; mt < 4; mt++)
            #pragma unroll
            for (int nt = 0; nt < 4; nt++)
                mma16816h(acc[mt][nt], ah[mt], bh[nt]);
    }
}

__global__ __launch_bounds__(256, 2) void k_gemm(
    int mode, const float* __restrict__ bias,
    const float* __restrict__ xres, float* __restrict__ outp)
{
    extern __shared__ char smem[];
    uint32_t sb = smem_u32(smem);
    int tid = threadIdx.x, lane = tid & 31, wid = tid >> 5;
    int n0 = blockIdx.x * 128, m0 = blockIdx.y * 128;
    int wm = (wid & 1) * 64, wn = (wid >> 1) * 32;
    const __half* B = mode ? g_woT : g_wiT;
    uint32_t buf0 = sb, buf1 = sb + BUF_B;
    float acc[4][4][4] = {};

    load_chunk(buf0, g_a16, B, m0, n0, 0, tid);
    asm volatile("cp.async.commit_group;" ::: "memory");
    load_chunk(buf1, g_a16, B, m0, n0, 64, tid);
    asm volatile("cp.async.commit_group;" ::: "memory");

    asm volatile("cp.async.wait_group 1;" ::: "memory");
    __syncthreads();
    compute_chunk(buf0, acc, wm, wn, lane);
    __syncthreads();
    load_chunk(buf0, g_a16, B, m0, n0, 128, tid);
    asm volatile("cp.async.commit_group;" ::: "memory");

    asm volatile("cp.async.wait_group 1;" ::: "memory");
    __syncthreads();
    compute_chunk(buf1, acc, wm, wn, lane);
    __syncthreads();
    load_chunk(buf1, g_a16, B, m0, n0, 192, tid);
    asm volatile("cp.async.commit_group;" ::: "memory");

    asm volatile("cp.async.wait_group 1;" ::: "memory");
    __syncthreads();
    compute_chunk(buf0, acc, wm, wn, lane);

    asm volatile("cp.async.wait_group 0;" ::: "memory");
    __syncthreads();
    compute_chunk(buf1, acc, wm, wn, lane);

    #pragma unroll
    for (int mt = 0; mt < 4; mt++) {
        int r0 = m0 + wm + mt*16 + (lane >> 2);
        #pragma unroll
        for (int nt = 0; nt < 4; nt++) {
            int col = n0 + wn + nt*8 + (lane & 3)*2;
            float2 bv = *(const float2*)(bias + col);
            float v0 = acc[mt][nt][0] + bv.x, v1 = acc[mt][nt][1] + bv.y;
            float v2 = acc[mt][nt][2] + bv.x, v3 = acc[mt][nt][3] + bv.y;
            if (mode == 0) {
                if (col >= 256) {
                    *(__half2*)(g_gate + (size_t)r0*Dn + col - 256) =
                        __floats2half2_rn(sigmoidf_(v0), sigmoidf_(v1));
                    *(__half2*)(g_gate + (size_t)(r0+8)*Dn + col - 256) =
                        __floats2half2_rn(sigmoidf_(v2), sigmoidf_(v3));
                } else {
                    *(__half2*)(g_xin + (size_t)r0*Dn + col) = __floats2half2_rn(v0, v1);
                    *(__half2*)(g_xin + (size_t)(r0+8)*Dn + col) = __floats2half2_rn(v2, v3);
                }
            } else {
                float2 x0 = *(const float2*)(xres + (size_t)r0*Dn + col);
                float2 x1 = *(const float2*)(xres + (size_t)(r0+8)*Dn + col);
                float2 o0 = {v0 + x0.x, v1 + x0.y};
                float2 o1 = {v2 + x1.x, v3 + x1.y};
                *(float2*)(outp + (size_t)r0*Dn + col) = o0;
                *(float2*)(outp + (size_t)(r0+8)*Dn + col) = o1;
            }
        }
    }
}

// =============== conv3x3+SiLU + ROW chunk scan (scalar, 256 thr) ==============
__global__ __launch_bounds__(256) void k_conv_rowscan(
    const float* __restrict__ conv_w, const float* __restrict__ conv_b,
    const float* __restrict__ a_logit, const float* __restrict__ ssm_b)
{
    int c = threadIdx.x;
    int b = blockIdx.x / Hn, h = blockIdx.x % Hn;

    float kw[3][3];
    const __half* rp[3];
    #pragma unroll
    for (int dh = 0; dh < 3; dh++) {
        int hh = h + dh - 1;
        bool v = (hh >= 0 && hh < Hn);
        float m = v ? 1.f : 0.f;
        #pragma unroll
        for (int dw = 0; dw < 3; dw++)
            kw[dh][dw] = m * conv_w[(dh*3 + dw) * Dn + c];
        rp[dh] = g_xin + ((size_t)(b*Hn + (v ? hh : 0)) * Wn) * Dn + c;
    }
    float bias = conv_b[c];

    float a = fminf(fmaxf(sigmoidf_(a_logit[c]), 1e-4f), 1.f - 1e-4f);
    float bb = ssm_b[c];
    float lf = 0.f, P = 0.f, ap = 1.f;

    float cA[3], cB[3];
    #pragma unroll
    for (int dh = 0; dh < 3; dh++) {
        cA[dh] = 0.f;
        cB[dh] = __half2float(rp[dh][0]);
    }

    __half* up = g_u + ((size_t)(b*Hn + h) * Wn) * Dn + c;

    for (int g = 0; g < 12; g++) {
        float nw[3][8];
        #pragma unroll
        for (int i = 0; i < 7; i++) {
            int col = g*8 + 1 + i;
            #pragma unroll
            for (int dh = 0; dh < 3; dh++)
                nw[dh][i] = __half2float(rp[dh][(size_t)col * Dn]);
        }
        {
            int col = g*8 + 8;
            bool ok = (col < Wn);
            int colc = ok ? col : (Wn-1);
            #pragma unroll
            for (int dh = 0; dh < 3; dh++)
                nw[dh][7] = ok ? __half2float(rp[dh][(size_t)colc * Dn]) : 0.f;
        }
        float seq[3][10];
        #pragma unroll
        for (int dh = 0; dh < 3; dh++) {
            seq[dh][0] = cA[dh]; seq[dh][1] = cB[dh];
            #pragma unroll
            for (int i = 0; i < 8; i++) seq[dh][2+i] = nw[dh][i];
        }
        #pragma unroll
        for (int i = 0; i < 8; i++) {
            float s = bias;
            #pragma unroll
            for (int dh = 0; dh < 3; dh++) {
                s += kw[dh][0]*seq[dh][i] + kw[dh][1]*seq[dh][i+1] + kw[dh][2]*seq[dh][i+2];
            }
            float u = s * sigmoidf_(s);
            up[(size_t)(g*8 + i) * Dn] = __float2half_rn(u);
            float bu = bb * u;
            lf = a * lf + bu;
            P  = fmaf(ap, bu, P);
            ap *= a;
        }
        #pragma unroll
        for (int dh = 0; dh < 3; dh++) { cA[dh] = seq[dh][8]; cB[dh] = seq[dh][9]; }
    }
    g_fin[0][0][b][h][c] = lf;
    g_fin[0][1][b][h][c] = P;
}

// =============== K3a: col local finals + fused scanB1(o=0) ===================
__global__ __launch_bounds__(128) void k_scanA_col(
    const float* __restrict__ a_logit, const float* __restrict__ ssm_b)
{
    if (blockIdx.x >= NCH) {
        scanB1_body(a_logit, blockIdx.y, 0, blockIdx.x - NCH, threadIdx.x);
        return;
    }
    int c = threadIdx.x * 2;
    int j = blockIdx.x, b = blockIdx.y;
    float2 al = *(const float2*)(a_logit + c);
    float ax = fminf(fmaxf(sigmoidf_(al.x), 1e-4f), 1.f - 1e-4f);
    float ay = fminf(fmaxf(sigmoidf_(al.y), 1e-4f), 1.f - 1e-4f);
    float2 bb = *(const float2*)(ssm_b + c);

    size_t base = ((size_t)b*Hn*Wn + (size_t)j) * Dn + c;
    const size_t stride = (size_t)Wn * Dn;

    float lfx=0.f, lfy=0.f, Px=0.f, Py=0.f, apx=1.f, apy=1.f;
    for (int g = 0; g < 6; g++) {
        __half2 t[16];
        #pragma unroll
        for (int i = 0; i < 16; i++) t[i] = *(const __half2*)(g_u + base + (size_t)(g*16 + i)*stride);
        #pragma unroll
        for (int i = 0; i < 16; i++) {
            float2 f = __half22float2(t[i]);
            float bux = bb.x * f.x, buy = bb.y * f.y;
            lfx = ax*lfx + bux;  lfy = ay*lfy + buy;
            Px = fmaf(apx, bux, Px); Py = fmaf(apy, buy, Py);
            apx *= ax; apy *= ay;
        }
    }
    *(float2*)&g_fin[1][0][b][j][c] = make_float2(lfx, lfy);
    *(float2*)&g_fin[1][1][b][j][c] = make_float2(Px, Py);
}

// =============== K3c: apply pass; o==0 grid fuses scanB1(o=1) =================
__global__ __launch_bounds__(128) void k_scanC(
    const float* __restrict__ a_logit, const float* __restrict__ ssm_b,
    const float* __restrict__ ssm_c,  const float* __restrict__ ssm_d, int o)
{
    if (blockIdx.x >= NCH) {
        scanB1_body(a_logit, blockIdx.y, 1, blockIdx.x - NCH, threadIdx.x);
        return;
    }
    int c = threadIdx.x * 2;
    int j = blockIdx.x, b = blockIdx.y;
    int gq = j >> 3, iq = j & 7;
    float2 al = *(const float2*)(a_logit + c);
    float ax = fminf(fmaxf(sigmoidf_(al.x), 1e-4f), 1.f - 1e-4f);
    float ay = fminf(fmaxf(sigmoidf_(al.y), 1e-4f), 1.f - 1e-4f);
    float invax = 1.f/ax, invay = 1.f/ay;
    float a96x = (float)exp(96.0 * log((double)ax));
    float a96y = (float)exp(96.0 * log((double)ay));
    float a2x = a96x*a96x, a2y = a96y*a96y;
    float a4x = a2x*a2x,  a4y = a2y*a2y;
    float a768x = a4x*a4x, a768y = a4y*a4y;
    float pFx = 1.f, pFy = 1.f, pBx = 1.f, pBy = 1.f;
    for (int k = 0; k < iq; k++)     { pFx *= a96x; pFy *= a96y; }
    for (int k = 0; k < 7 - iq; k++) { pBx *= a96x; pBy *= a96y; }
    float2 bb = *(const float2*)(ssm_b + c);
    float2 cc = *(const float2*)(ssm_c + c);
    float2 dd = *(const float2*)(ssm_d + c);

    float2 gfv[12], gbv[12];
    #pragma unroll
    for (int g = 0; g < 12; g++) {
        gfv[g] = *(const float2*)&g_gf[o][0][b][g][c];
        gbv[g] = *(const float2*)&g_gf[o][1][b][g][c];
    }
    float gc0x = 0.f, gc0y = 0.f;
    for (int g = 0; g < gq; g++) { gc0x = a768x*gc0x + gfv[g].x; gc0y = a768y*gc0y + gfv[g].y; }
    float gc1x = 0.f, gc1y = 0.f;
    for (int g = 11; g > gq; g--) { gc1x = a768x*gc1x + gbv[g].x; gc1y = a768y*gc1y + gbv[g].y; }

    float2 lc0 = *(const float2*)&g_carry[o][0][b][j][c];
    float2 lc1 = *(const float2*)&g_carry[o][1][b][j][c];
    float2 sf = make_float2(lc0.x + pFx*gc0x, lc0.y + pFy*gc0y);
    float cb96x = a96x * (lc1.x + pBx*gc1x);
    float cb96y = a96y * (lc1.y + pBy*gc1y);
    float2 Tt = *(const float2*)&g_fin[o][1][b][j][c];

    size_t base, stride;
    if (o == 0) { base = ((size_t)(b*Hn + j) * Wn) * Dn + c;      stride = Dn; }
    else        { base = ((size_t)b*Hn*Wn + (size_t)j) * Dn + c;  stride = (size_t)Wn * Dn; }

    float Px=0.f, Py=0.f, apx=1.f, apy=1.f, rapx=1.f, rapy=1.f;
    if (o == 0) {
        for (int g = 0; g < 6; g++) {
            __half2 t[16];
            #pragma unroll
            for (int i = 0; i < 16; i++) t[i] = *(const __half2*)(g_u + base + (size_t)(g*16 + i)*stride);
            #pragma unroll
            for (int i = 0; i < 16; i++) {
                size_t addr = base + (size_t)(g*16 + i) * stride;
                float2 uf = __half22float2(t[i]);
                sf.x = ax*sf.x + bb.x*uf.x;
                sf.y = ay*sf.y + bb.y*uf.y;
                float sbx = (Tt.x - Px + cb96x) * rapx;
                float sby = (Tt.y - Py + cb96y) * rapy;
                float ctx = 0.25f * cc.x * (sf.x + sbx);
                float cty = 0.25f * cc.y * (sf.y + sby);
                *(__half2*)(g_y + addr) = __floats2half2_rn(ctx + dd.x*uf.x, cty + dd.y*uf.y);
                Px = fmaf(apx, bb.x*uf.x, Px);
                Py = fmaf(apy, bb.y*uf.y, Py);
                apx *= ax; apy *= ay;
                rapx *= invax; rapy *= invay;
            }
        }
    } else {
        for (int g = 0; g < 12; g++) {
            __half2 t[8], yv[8], gv[8];
            #pragma unroll
            for (int i = 0; i < 8; i++) t[i] = *(const __half2*)(g_u + base + (size_t)(g*8 + i)*stride);
            #pragma unroll
            for (int i = 0; i < 8; i++) yv[i] = *(const __half2*)(g_y + base + (size_t)(g*8 + i)*stride);
            #pragma unroll
            for (int i = 0; i < 8; i++) gv[i] = *(const __half2*)(g_gate + base + (size_t)(g*8 + i)*stride);
            #pragma unroll
            for (int i = 0; i < 8; i++) {
                size_t addr = base + (size_t)(g*8 + i) * stride;
                float2 uf = __half22float2(t[i]);
                sf.x = ax*sf.x + bb.x*uf.x;
                sf.y = ay*sf.y + bb.y*uf.y;
                float sbx = (Tt.x - Px + cb96x) * rapx;
                float sby = (Tt.y - Py + cb96y) * rapy;
                float ctx = 0.25f * cc.x * (sf.x + sbx);
                float cty = 0.25f * cc.y * (sf.y + sby);
                float2 yf = __half22float2(yv[i]);
                float2 gf = __half22float2(gv[i]);
                *(__half2*)(g_a16 + addr) =
                    __floats2half2_rn((yf.x + ctx) * gf.x, (yf.y + cty) * gf.y);
                Px = fmaf(apx, bb.x*uf.x, Px);
                Py = fmaf(apy, bb.y*uf.y, Py);
                apx *= ax; apy *= ay;
                rapx *= invax; rapy *= invay;
            }
        }
    }
}

// ==============================================================================
extern "C" void kernel_launch(void* const* d_in, const int* in_sizes, int n_in,
                              void* d_out, int out_size)
{
    const float* x       = (const float*)d_in[0];
    const float* ln_g    = (const float*)d_in[1];
    const float* ln_b    = (const float*)d_in[2];
    const float* w_in    = (const float*)d_in[3];
    const float* b_in    = (const float*)d_in[4];
    const float* conv_w  = (const float*)d_in[5];
    const float* conv_b  = (const float*)d_in[6];
    const float* a_logit = (const float*)d_in[7];
    const float* ssm_b   = (const float*)d_in[8];
    const float* ssm_c   = (const float*)d_in[9];
    const float* ssm_d   = (const float*)d_in[10];
    const float* w_out   = (const float*)d_in[11];
    const float* b_out   = (const float*)d_in[12];
    float* out = (float*)d_out;

    cudaFuncSetAttribute(k_gemm, cudaFuncAttributeMaxDynamicSharedMemorySize, SMEM_GEMM);

    k_ln_split<<<NPIX/32 + 768, 256>>>(x, ln_g, ln_b, w_in, w_out);
    k_gemm<<<dim3(4, NPIX/128), 256, SMEM_GEMM>>>(0, b_in, nullptr, nullptr);
    k_conv_rowscan<<<Bn*Hn, 256>>>(conv_w, conv_b, a_logit, ssm_b);
    k_scanA_col<<<dim3(NCH + 12, Bn), 128>>>(a_logit, ssm_b);
    k_scanC<<<dim3(NCH + 12, Bn), 128>>>(a_logit, ssm_b, ssm_c, ssm_d, 0);
    k_scanC<<<dim3(NCH, Bn), 128>>>(a_logit, ssm_b, ssm_c, ssm_d, 1);
    k_gemm<<<dim3(2, NPIX/128), 256, SMEM_GEMM>>>(1, b_out, x, out);
}

// round 17
// speedup vs baseline: 1.1321x; 1.0319x over previous
#include <cuda_runtime.h>
#include <cuda_fp16.h>
#include <math.h>
#include <stdint.h>

#define Bn 8
#define Hn 96
#define Wn 96
#define Dn 256
#define NPIX (Bn*Hn*Wn)          // 73728
#define NCH 96

typedef unsigned long long u64;

// ---------------- scratch (device globals) ------------------------------------
__device__ __half g_xin[NPIX*Dn];
__device__ __half g_gate[NPIX*Dn];
__device__ __half g_u[NPIX*Dn];
__device__ __half g_y[NPIX*Dn];
__device__ __half g_a16[NPIX*Dn];                        // GEMM A operand (fp16)
__device__ float  g_fin[2][2][Bn][NCH][Dn];
__device__ float  g_carry[2][2][Bn][NCH][Dn];            // in-group local carries
__device__ float  g_gf[2][2][Bn][12][Dn];                // group finals
__device__ __half g_wiT[512*256];                        // w_in^T [n][k] fp16
__device__ __half g_woT[256*256];                        // w_out^T [n][k] fp16

__device__ __forceinline__ float sigmoidf_(float v){
    return __fdividef(1.f, 1.f + __expf(-v));
}

__device__ __forceinline__ uint32_t smem_u32(const void* p){
    uint32_t a;
    asm("{ .reg .u64 t; cvta.to.shared.u64 t, %1; cvt.u32.u64 %0, t; }" : "=r"(a) : "l"(p));
    return a;
}
__device__ __forceinline__ void cp16(uint32_t sdst, const void* gsrc){
    asm volatile("cp.async.cg.shared.global [%0], [%1], 16;" :: "r"(sdst), "l"(gsrc));
}
__device__ __forceinline__ void ldsm4(uint32_t* r, uint32_t a){
    asm volatile("ldmatrix.sync.aligned.m8n8.x4.shared.b16 {%0,%1,%2,%3}, [%4];"
        : "=r"(r[0]),"=r"(r[1]),"=r"(r[2]),"=r"(r[3]) : "r"(a));
}
__device__ __forceinline__ void mma16816h(float* d, const uint32_t* a, const uint32_t* b){
    asm volatile("mma.sync.aligned.m16n8k16.row.col.f32.f16.f16.f32 "
        "{%0,%1,%2,%3}, {%4,%5,%6,%7}, {%8,%9}, {%0,%1,%2,%3};"
        : "+f"(d[0]), "+f"(d[1]), "+f"(d[2]), "+f"(d[3])
        : "r"(a[0]), "r"(a[1]), "r"(a[2]), "r"(a[3]), "r"(b[0]), "r"(b[1]));
}
__device__ __forceinline__ __half2 ldcs_h2(const __half* p){
    return __ldcs((const __half2*)p);
}

// =============== scanB1 body (group-local carry scans, float2) =================
__device__ __forceinline__ void scanB1_body(const float* a_logit, int b, int o, int g, int tid)
{
    int c = tid * 2;
    float2 al = *(const float2*)(a_logit + c);
    float ax = fminf(fmaxf(sigmoidf_(al.x), 1e-4f), 1.f - 1e-4f);
    float ay = fminf(fmaxf(sigmoidf_(al.y), 1e-4f), 1.f - 1e-4f);
    float a96x = (float)exp(96.0 * log((double)ax));
    float a96y = (float)exp(96.0 * log((double)ay));

    float2 t[8];
    #pragma unroll
    for (int i = 0; i < 8; i++) t[i] = *(const float2*)&g_fin[o][0][b][g*8 + i][c];
    float cx = 0.f, cy = 0.f;
    #pragma unroll
    for (int i = 0; i < 8; i++) {
        *(float2*)&g_carry[o][0][b][g*8 + i][c] = make_float2(cx, cy);
        cx = a96x*cx + t[i].x;  cy = a96y*cy + t[i].y;
    }
    *(float2*)&g_gf[o][0][b][g][c] = make_float2(cx, cy);

    #pragma unroll
    for (int i = 0; i < 8; i++) t[i] = *(const float2*)&g_fin[o][1][b][g*8 + i][c];
    cx = 0.f; cy = 0.f;
    #pragma unroll
    for (int i = 7; i >= 0; i--) {
        *(float2*)&g_carry[o][1][b][g*8 + i][c] = make_float2(cx, cy);
        cx = a96x*cx + t[i].x;  cy = a96y*cy + t[i].y;
    }
    *(float2*)&g_gf[o][1][b][g][c] = make_float2(cx, cy);
}

// =============== prep: LN -> fp16 A (batched loads); fused weight transpose ===
__global__ __launch_bounds__(256) void k_ln_split(
    const float* __restrict__ x, const float* __restrict__ ln_g,
    const float* __restrict__ ln_b, const float* __restrict__ w_in,
    const float* __restrict__ w_out)
{
    if (blockIdx.x >= NPIX/32) {
        int n = blockIdx.x - NPIX/32;
        int k = threadIdx.x;
        if (n < 512) {
            g_wiT[(size_t)n*256 + k] = __float2half_rn(w_in[(size_t)k * 512 + n]);
        } else {
            int nn = n - 512;
            g_woT[(size_t)nn*256 + k] = __float2half_rn(w_out[(size_t)k * 256 + nn]);
        }
        return;
    }
    int lane = threadIdx.x & 31, warp = threadIdx.x >> 5;
    int row0 = blockIdx.x * 32 + warp * 4;

    float4 v[4][2];
    #pragma unroll
    for (int rr = 0; rr < 4; rr++) {
        const float* xr = x + (size_t)(row0 + rr) * Dn;
        v[rr][0] = __ldcs((const float4*)(xr + lane*4));
        v[rr][1] = __ldcs((const float4*)(xr + 128 + lane*4));
    }

    float4 gg0 = *(const float4*)(ln_g + lane*4);
    float4 gg1 = *(const float4*)(ln_g + 128 + lane*4);
    float4 be0 = *(const float4*)(ln_b + lane*4);
    float4 be1 = *(const float4*)(ln_b + 128 + lane*4);

    #pragma unroll
    for (int rr = 0; rr < 4; rr++) {
        float4 a = v[rr][0], b = v[rr][1];
        float s  = a.x+a.y+a.z+a.w + b.x+b.y+b.z+b.w;
        float s2 = a.x*a.x+a.y*a.y+a.z*a.z+a.w*a.w
                 + b.x*b.x+b.y*b.y+b.z*b.z+b.w*b.w;
        #pragma unroll
        for (int off = 16; off; off >>= 1) {
            s  += __shfl_xor_sync(0xffffffffu, s,  off);
            s2 += __shfl_xor_sync(0xffffffffu, s2, off);
        }
        float mu = s * (1.f/256.f);
        float rstd = rsqrtf(s2 * (1.f/256.f) - mu*mu + 1e-5f);
        __half2 p0 = __floats2half2_rn((a.x - mu)*rstd*gg0.x + be0.x,
                                       (a.y - mu)*rstd*gg0.y + be0.y);
        __half2 p1 = __floats2half2_rn((a.z - mu)*rstd*gg0.z + be0.z,
                                       (a.w - mu)*rstd*gg0.w + be0.w);
        __half2 p2 = __floats2half2_rn((b.x - mu)*rstd*gg1.x + be1.x,
                                       (b.y - mu)*rstd*gg1.y + be1.y);
        __half2 p3 = __floats2half2_rn((b.z - mu)*rstd*gg1.z + be1.z,
                                       (b.w - mu)*rstd*gg1.w + be1.w);
        __half2* d0 = (__half2*)(g_a16 + (size_t)(row0 + rr)*Dn + lane*4);
        __half2* d1 = (__half2*)(g_a16 + (size_t)(row0 + rr)*Dn + 128 + lane*4);
        d0[0] = p0; d0[1] = p1;
        d1[0] = p2; d1[1] = p3;
    }
}

// =============== HMMA fp16 single-term GEMM (2 CTAs/SM) ========================
#define TILE_B 16384
#define BUF_B  (2*TILE_B)
#define SMEM_GEMM (2*BUF_B)

__device__ __forceinline__ void load_chunk(
    uint32_t sbuf, const __half* __restrict__ A, const __half* __restrict__ B,
    int m0, int n0, int kc, int tid)
{
    #pragma unroll
    for (int t = 0; t < 2; t++) {
        const __half* src = t ? B : A;
        int r0 = t ? n0 : m0;
        #pragma unroll
        for (int q = 0; q < 4; q++) {
            int u = q*256 + tid;
            int r = u >> 3, g = u & 7;
            uint32_t boff = r*128 + g*16;
            uint32_t swo = boff ^ ((boff>>3)&0x70);
            cp16(sbuf + t*TILE_B + swo, src + (size_t)(r0 + r)*Dn + kc + g*8);
        }
    }
}

__device__ __forceinline__ void compute_chunk(
    uint32_t sbuf, float acc[4][4][4], int wm, int wn, int lane)
{
    uint32_t aA = sbuf, aB = sbuf + TILE_B;
    int arow = wm + (lane&7) + 8*((lane>>3)&1);
    int akb0 = 16*(lane>>4);
    int brow = wn + 8*(lane>>4) + (lane&7);
    int bkb0 = 16*((lane>>3)&1);
    #pragma unroll
    for (int ks = 0; ks < 4; ks++) {
        int kb = ks*32;
        uint32_t ah[4][4], bh[4][2];
        #pragma unroll
        for (int mt = 0; mt < 4; mt++) {
            uint32_t boff = (uint32_t)(arow + mt*16)*128 + kb + akb0;
            uint32_t swo = boff ^ ((boff>>3)&0x70);
            ldsm4(ah[mt], aA + swo);
        }
        #pragma unroll
        for (int p = 0; p < 2; p++) {
            uint32_t boff = (uint32_t)(brow + p*16)*128 + kb + bkb0;
            uint32_t swo = boff ^ ((boff>>3)&0x70);
            uint32_t t[4];
            ldsm4(t, aB + swo);
            bh[p*2][0]=t[0]; bh[p*2][1]=t[1]; bh[p*2+1][0]=t[2]; bh[p*2+1][1]=t[3];
        }
        #pragma unroll
        for (int mt = 0; mt < 4; mt++)
            #pragma unroll
            for (int nt = 0; nt < 4; nt++)
                mma16816h(acc[mt][nt], ah[mt], bh[nt]);
    }
}

__global__ __launch_bounds__(256, 2) void k_gemm(
    int mode, const float* __restrict__ bias,
    const float* __restrict__ xres, float* __restrict__ outp)
{
    extern __shared__ char smem[];
    uint32_t sb = smem_u32(smem);
    int tid = threadIdx.x, lane = tid & 31, wid = tid >> 5;
    int n0 = blockIdx.x * 128, m0 = blockIdx.y * 128;
    int wm = (wid & 1) * 64, wn = (wid >> 1) * 32;
    const __half* B = mode ? g_woT : g_wiT;
    uint32_t buf0 = sb, buf1 = sb + BUF_B;
    float acc[4][4][4] = {};

    load_chunk(buf0, g_a16, B, m0, n0, 0, tid);
    asm volatile("cp.async.commit_group;" ::: "memory");
    load_chunk(buf1, g_a16, B, m0, n0, 64, tid);
    asm volatile("cp.async.commit_group;" ::: "memory");

    asm volatile("cp.async.wait_group 1;" ::: "memory");
    __syncthreads();
    compute_chunk(buf0, acc, wm, wn, lane);
    __syncthreads();
    load_chunk(buf0, g_a16, B, m0, n0, 128, tid);
    asm volatile("cp.async.commit_group;" ::: "memory");

    asm volatile("cp.async.wait_group 1;" ::: "memory");
    __syncthreads();
    compute_chunk(buf1, acc, wm, wn, lane);
    __syncthreads();
    load_chunk(buf1, g_a16, B, m0, n0, 192, tid);
    asm volatile("cp.async.commit_group;" ::: "memory");

    asm volatile("cp.async.wait_group 1;" ::: "memory");
    __syncthreads();
    compute_chunk(buf0, acc, wm, wn, lane);

    asm volatile("cp.async.wait_group 0;" ::: "memory");
    __syncthreads();
    compute_chunk(buf1, acc, wm, wn, lane);

    #pragma unroll
    for (int mt = 0; mt < 4; mt++) {
        int r0 = m0 + wm + mt*16 + (lane >> 2);
        if (mode == 0) {
            #pragma unroll
            for (int nt = 0; nt < 4; nt++) {
                int col = n0 + wn + nt*8 + (lane & 3)*2;
                float2 bv = *(const float2*)(bias + col);
                float v0 = acc[mt][nt][0] + bv.x, v1 = acc[mt][nt][1] + bv.y;
                float v2 = acc[mt][nt][2] + bv.x, v3 = acc[mt][nt][3] + bv.y;
                if (col >= 256) {
                    *(__half2*)(g_gate + (size_t)r0*Dn + col - 256) =
                        __floats2half2_rn(sigmoidf_(v0), sigmoidf_(v1));
                    *(__half2*)(g_gate + (size_t)(r0+8)*Dn + col - 256) =
                        __floats2half2_rn(sigmoidf_(v2), sigmoidf_(v3));
                } else {
                    *(__half2*)(g_xin + (size_t)r0*Dn + col) = __floats2half2_rn(v0, v1);
                    *(__half2*)(g_xin + (size_t)(r0+8)*Dn + col) = __floats2half2_rn(v2, v3);
                }
            }
        } else {
            // hoist residual loads (8 independent LDG.64)
            float2 x0[4], x1[4];
            #pragma unroll
            for (int nt = 0; nt < 4; nt++) {
                int col = n0 + wn + nt*8 + (lane & 3)*2;
                x0[nt] = __ldcs((const float2*)(xres + (size_t)r0*Dn + col));
                x1[nt] = __ldcs((const float2*)(xres + (size_t)(r0+8)*Dn + col));
            }
            #pragma unroll
            for (int nt = 0; nt < 4; nt++) {
                int col = n0 + wn + nt*8 + (lane & 3)*2;
                float2 bv = *(const float2*)(bias + col);
                float2 o0 = {acc[mt][nt][0] + bv.x + x0[nt].x, acc[mt][nt][1] + bv.y + x0[nt].y};
                float2 o1 = {acc[mt][nt][2] + bv.x + x1[nt].x, acc[mt][nt][3] + bv.y + x1[nt].y};
                *(float2*)(outp + (size_t)r0*Dn + col) = o0;
                *(float2*)(outp + (size_t)(r0+8)*Dn + col) = o1;
            }
        }
    }
}

// =============== conv3x3+SiLU + ROW chunk scan (scalar, 256 thr) ==============
__global__ __launch_bounds__(256) void k_conv_rowscan(
    const float* __restrict__ conv_w, const float* __restrict__ conv_b,
    const float* __restrict__ a_logit, const float* __restrict__ ssm_b)
{
    int c = threadIdx.x;
    int b = blockIdx.x / Hn, h = blockIdx.x % Hn;

    float kw[3][3];
    const __half* rp[3];
    #pragma unroll
    for (int dh = 0; dh < 3; dh++) {
        int hh = h + dh - 1;
        bool v = (hh >= 0 && hh < Hn);
        float m = v ? 1.f : 0.f;
        #pragma unroll
        for (int dw = 0; dw < 3; dw++)
            kw[dh][dw] = m * conv_w[(dh*3 + dw) * Dn + c];
        rp[dh] = g_xin + ((size_t)(b*Hn + (v ? hh : 0)) * Wn) * Dn + c;
    }
    float bias = conv_b[c];

    float a = fminf(fmaxf(sigmoidf_(a_logit[c]), 1e-4f), 1.f - 1e-4f);
    float bb = ssm_b[c];
    float lf = 0.f, P = 0.f, ap = 1.f;

    float cA[3], cB[3];
    #pragma unroll
    for (int dh = 0; dh < 3; dh++) {
        cA[dh] = 0.f;
        cB[dh] = __half2float(rp[dh][0]);
    }

    __half* up = g_u + ((size_t)(b*Hn + h) * Wn) * Dn + c;

    for (int g = 0; g < 12; g++) {
        float nw[3][8];
        #pragma unroll
        for (int i = 0; i < 7; i++) {
            int col = g*8 + 1 + i;
            #pragma unroll
            for (int dh = 0; dh < 3; dh++)
                nw[dh][i] = __half2float(rp[dh][(size_t)col * Dn]);
        }
        {
            int col = g*8 + 8;
            bool ok = (col < Wn);
            int colc = ok ? col : (Wn-1);
            #pragma unroll
            for (int dh = 0; dh < 3; dh++)
                nw[dh][7] = ok ? __half2float(rp[dh][(size_t)colc * Dn]) : 0.f;
        }
        float seq[3][10];
        #pragma unroll
        for (int dh = 0; dh < 3; dh++) {
            seq[dh][0] = cA[dh]; seq[dh][1] = cB[dh];
            #pragma unroll
            for (int i = 0; i < 8; i++) seq[dh][2+i] = nw[dh][i];
        }
        #pragma unroll
        for (int i = 0; i < 8; i++) {
            float s = bias;
            #pragma unroll
            for (int dh = 0; dh < 3; dh++) {
                s += kw[dh][0]*seq[dh][i] + kw[dh][1]*seq[dh][i+1] + kw[dh][2]*seq[dh][i+2];
            }
            float u = s * sigmoidf_(s);
            up[(size_t)(g*8 + i) * Dn] = __float2half_rn(u);
            float bu = bb * u;
            lf = a * lf + bu;
            P  = fmaf(ap, bu, P);
            ap *= a;
        }
        #pragma unroll
        for (int dh = 0; dh < 3; dh++) { cA[dh] = seq[dh][8]; cB[dh] = seq[dh][9]; }
    }
    g_fin[0][0][b][h][c] = lf;
    g_fin[0][1][b][h][c] = P;
}

// =============== K3a: col local finals + fused scanB1(o=0) ===================
__global__ __launch_bounds__(128) void k_scanA_col(
    const float* __restrict__ a_logit, const float* __restrict__ ssm_b)
{
    if (blockIdx.x >= NCH) {
        scanB1_body(a_logit, blockIdx.y, 0, blockIdx.x - NCH, threadIdx.x);
        return;
    }
    int c = threadIdx.x * 2;
    int j = blockIdx.x, b = blockIdx.y;
    float2 al = *(const float2*)(a_logit + c);
    float ax = fminf(fmaxf(sigmoidf_(al.x), 1e-4f), 1.f - 1e-4f);
    float ay = fminf(fmaxf(sigmoidf_(al.y), 1e-4f), 1.f - 1e-4f);
    float2 bb = *(const float2*)(ssm_b + c);

    size_t base = ((size_t)b*Hn*Wn + (size_t)j) * Dn + c;
    const size_t stride = (size_t)Wn * Dn;

    float lfx=0.f, lfy=0.f, Px=0.f, Py=0.f, apx=1.f, apy=1.f;
    for (int g = 0; g < 6; g++) {
        __half2 t[16];
        #pragma unroll
        for (int i = 0; i < 16; i++) t[i] = *(const __half2*)(g_u + base + (size_t)(g*16 + i)*stride);
        #pragma unroll
        for (int i = 0; i < 16; i++) {
            float2 f = __half22float2(t[i]);
            float bux = bb.x * f.x, buy = bb.y * f.y;
            lfx = ax*lfx + bux;  lfy = ay*lfy + buy;
            Px = fmaf(apx, bux, Px); Py = fmaf(apy, buy, Py);
            apx *= ax; apy *= ay;
        }
    }
    *(float2*)&g_fin[1][0][b][j][c] = make_float2(lfx, lfy);
    *(float2*)&g_fin[1][1][b][j][c] = make_float2(Px, Py);
}

// =============== K3c: apply pass; o==0 grid fuses scanB1(o=1) =================
__global__ __launch_bounds__(128) void k_scanC(
    const float* __restrict__ a_logit, const float* __restrict__ ssm_b,
    const float* __restrict__ ssm_c,  const float* __restrict__ ssm_d, int o)
{
    if (blockIdx.x >= NCH) {
        scanB1_body(a_logit, blockIdx.y, 1, blockIdx.x - NCH, threadIdx.x);
        return;
    }
    int c = threadIdx.x * 2;
    int j = blockIdx.x, b = blockIdx.y;
    int gq = j >> 3, iq = j & 7;
    float2 al = *(const float2*)(a_logit + c);
    float ax = fminf(fmaxf(sigmoidf_(al.x), 1e-4f), 1.f - 1e-4f);
    float ay = fminf(fmaxf(sigmoidf_(al.y), 1e-4f), 1.f - 1e-4f);
    float invax = 1.f/ax, invay = 1.f/ay;
    float a96x = (float)exp(96.0 * log((double)ax));
    float a96y = (float)exp(96.0 * log((double)ay));
    float a2x = a96x*a96x, a2y = a96y*a96y;
    float a4x = a2x*a2x,  a4y = a2y*a2y;
    float a768x = a4x*a4x, a768y = a4y*a4y;
    float pFx = 1.f, pFy = 1.f, pBx = 1.f, pBy = 1.f;
    for (int k = 0; k < iq; k++)     { pFx *= a96x; pFy *= a96y; }
    for (int k = 0; k < 7 - iq; k++) { pBx *= a96x; pBy *= a96y; }
    float2 bb = *(const float2*)(ssm_b + c);
    float2 cc = *(const float2*)(ssm_c + c);
    float2 dd = *(const float2*)(ssm_d + c);

    float2 gfv[12], gbv[12];
    #pragma unroll
    for (int g = 0; g < 12; g++) {
        gfv[g] = *(const float2*)&g_gf[o][0][b][g][c];
        gbv[g] = *(const float2*)&g_gf[o][1][b][g][c];
    }
    float gc0x = 0.f, gc0y = 0.f;
    for (int g = 0; g < gq; g++) { gc0x = a768x*gc0x + gfv[g].x; gc0y = a768y*gc0y + gfv[g].y; }
    float gc1x = 0.f, gc1y = 0.f;
    for (int g = 11; g > gq; g--) { gc1x = a768x*gc1x + gbv[g].x; gc1y = a768y*gc1y + gbv[g].y; }

    float2 lc0 = *(const float2*)&g_carry[o][0][b][j][c];
    float2 lc1 = *(const float2*)&g_carry[o][1][b][j][c];
    float2 sf = make_float2(lc0.x + pFx*gc0x, lc0.y + pFy*gc0y);
    float cb96x = a96x * (lc1.x + pBx*gc1x);
    float cb96y = a96y * (lc1.y + pBy*gc1y);
    float2 Tt = *(const float2*)&g_fin[o][1][b][j][c];

    size_t base, stride;
    if (o == 0) { base = ((size_t)(b*Hn + j) * Wn) * Dn + c;      stride = Dn; }
    else        { base = ((size_t)b*Hn*Wn + (size_t)j) * Dn + c;  stride = (size_t)Wn * Dn; }

    float Px=0.f, Py=0.f, apx=1.f, apy=1.f, rapx=1.f, rapy=1.f;
    if (o == 0) {
        for (int g = 0; g < 6; g++) {
            __half2 t[16];
            #pragma unroll
            for (int i = 0; i < 16; i++) t[i] = *(const __half2*)(g_u + base + (size_t)(g*16 + i)*stride);
            #pragma unroll
            for (int i = 0; i < 16; i++) {
                size_t addr = base + (size_t)(g*16 + i) * stride;
                float2 uf = __half22float2(t[i]);
                sf.x = ax*sf.x + bb.x*uf.x;
                sf.y = ay*sf.y + bb.y*uf.y;
                float sbx = (Tt.x - Px + cb96x) * rapx;
                float sby = (Tt.y - Py + cb96y) * rapy;
                float ctx = 0.25f * cc.x * (sf.x + sbx);
                float cty = 0.25f * cc.y * (sf.y + sby);
                __stcs((__half2*)(g_y + addr),
                       __floats2half2_rn(ctx + dd.x*uf.x, cty + dd.y*uf.y));
                Px = fmaf(apx, bb.x*uf.x, Px);
                Py = fmaf(apy, bb.y*uf.y, Py);
                apx *= ax; apy *= ay;
                rapx *= invax; rapy *= invay;
            }
        }
    } else {
        for (int g = 0; g < 12; g++) {
            __half2 t[8], yv[8], gv[8];
            #pragma unroll
            for (int i = 0; i < 8; i++) t[i] = ldcs_h2(g_u + base + (size_t)(g*8 + i)*stride);
            #pragma unroll
            for (int i = 0; i < 8; i++) yv[i] = ldcs_h2(g_y + base + (size_t)(g*8 + i)*stride);
            #pragma unroll
            for (int i = 0; i < 8; i++) gv[i] = ldcs_h2(g_gate + base + (size_t)(g*8 + i)*stride);
            #pragma unroll
            for (int i = 0; i < 8; i++) {
                size_t addr = base + (size_t)(g*8 + i) * stride;
                float2 uf = __half22float2(t[i]);
                sf.x = ax*sf.x + bb.x*uf.x;
                sf.y = ay*sf.y + bb.y*uf.y;
                float sbx = (Tt.x - Px + cb96x) * rapx;
                float sby = (Tt.y - Py + cb96y) * rapy;
                float ctx = 0.25f * cc.x * (sf.x + sbx);
                float cty = 0.25f * cc.y * (sf.y + sby);
                float2 yf = __half22float2(yv[i]);
                float2 gf = __half22float2(gv[i]);
                *(__half2*)(g_a16 + addr) =
                    __floats2half2_rn((yf.x + ctx) * gf.x, (yf.y + cty) * gf.y);
                Px = fmaf(apx, bb.x*uf.x, Px);
                Py = fmaf(apy, bb.y*uf.y, Py);
                apx *= ax; apy *= ay;
                rapx *= invax; rapy *= invay;
            }
        }
    }
}

// ==============================================================================
extern "C" void kernel_launch(void* const* d_in, const int* in_sizes, int n_in,
                              void* d_out, int out_size)
{
    const float* x       = (const float*)d_in[0];
    const float* ln_g    = (const float*)d_in[1];
    const float* ln_b    = (const float*)d_in[2];
    const float* w_in    = (const float*)d_in[3];
    const float* b_in    = (const float*)d_in[4];
    const float* conv_w  = (const float*)d_in[5];
    const float* conv_b  = (const float*)d_in[6];
    const float* a_logit = (const float*)d_in[7];
    const float* ssm_b   = (const float*)d_in[8];
    const float* ssm_c   = (const float*)d_in[9];
    const float* ssm_d   = (const float*)d_in[10];
    const float* w_out   = (const float*)d_in[11];
    const float* b_out   = (const float*)d_in[12];
    float* out = (float*)d_out;

    cudaFuncSetAttribute(k_gemm, cudaFuncAttributeMaxDynamicSharedMemorySize, SMEM_GEMM);

    k_ln_split<<<NPIX/32 + 768, 256>>>(x, ln_g, ln_b, w_in, w_out);
    k_gemm<<<dim3(4, NPIX/128), 256, SMEM_GEMM>>>(0, b_in, nullptr, nullptr);
    k_conv_rowscan<<<Bn*Hn, 256>>>(conv_w, conv_b, a_logit, ssm_b);
    k_scanA_col<<<dim3(NCH + 12, Bn), 128>>>(a_logit, ssm_b);
    k_scanC<<<dim3(NCH + 12, Bn), 128>>>(a_logit, ssm_b, ssm_c, ssm_d, 0);
    k_scanC<<<dim3(NCH, Bn), 128>>>(a_logit, ssm_b, ssm_c, ssm_d, 1);
    k_gemm<<<dim3(2, NPIX/128), 256, SMEM_GEMM>>>(1, b_out, x, out);
}